// round 15
// baseline (speedup 1.0000x reference)
#include <cuda_runtime.h>
#include <cuda_bf16.h>
#include <math_constants.h>

// Problem constants (fixed shapes for this problem instance)
#define HH   128
#define WW   128
#define FF   1000
#define KK   8
#define NPIX (HH * WW)            // 16384
#define NSEC (NPIX * KK)          // 131072 elements per (B,H,W,K) section
#define EPSF 1e-8f
#define BIGF 1e10f

#define TILES_X 8                 // 8x8 tiles of 16x16 pixels
#define NTILES  64
#define TPAD    1e-5f             // conservative tile-bound padding
#define ETHR   (-1e-5f)           // edge-corner reject threshold (covers fp error)
#define SCAP   512                // smem staging cap (post-SAT len ~200-300; tail path covers overflow)

// Per-face affine edge coefficients (w_i = b_i*px + a_i*py + g_i):
//  g_cA[f] = (b0, a0, g0, b1)
//  g_cB[f] = (a1, g1, b2, a2)
//  g_cC[f] = (g2, szz0, szz1, szz2)   szz_i = s*z_j*z_k, s=sign(area), NaN if degenerate
//  g_cZ[f] = s*z0*z1*z2
__device__ float4 g_cA[FF];
__device__ float4 g_cB[FF];
__device__ float4 g_cC[FF];
__device__ float  g_cZ[FF];
__device__ int    g_list[NTILES * FF];   // per-tile face lists (ascending)
__device__ int    g_cnt[NTILES];

// ONE prep kernel: 64 blocks (one per tile) x 256 threads.
// Phase A: block b computes coefficients for faces [b*16, b*16+16).
// Phase B: block b bins all faces against its tile: bbox SAT + edge-normal SAT
//          (exact conservative triangle-vs-rect overlap).
__global__ __launch_bounds__(256) void prep_bin(const float* __restrict__ verts,
                                                const int* __restrict__ faces) {
    __shared__ unsigned s_mask[8][4];
    __shared__ int s_wcnt[8];
    __shared__ int s_woff[8];

    int tile = blockIdx.x;
    int tid  = threadIdx.x;
    int warp = tid >> 5;
    int lane = tid & 31;

    // ---- Phase A: coefficients for this block's 16 faces.
    {
        int f = tile * 16 + tid;
        if (tid < 16 && f < FF) {
            int i0 = faces[f * 3 + 0];
            int i1 = faces[f * 3 + 1];
            int i2 = faces[f * 3 + 2];
            float x0 = verts[i0*3+0], y0 = verts[i0*3+1], z0 = verts[i0*3+2];
            float x1 = verts[i1*3+0], y1 = verts[i1*3+1], z1 = verts[i1*3+2];
            float x2 = verts[i2*3+0], y2 = verts[i2*3+1], z2 = verts[i2*3+2];
            float area = (x1 - x0) * (y2 - y0) - (y1 - y0) * (x2 - x0);
            float s;
            if (area > EPSF)       s = 1.0f;
            else if (area < -EPSF) s = -1.0f;
            else                   s = CUDART_NAN_F;  // NaN => inside-test fails
            // w0 = (x2-x1)(py-y1) - (y2-y1)(px-x1) = b0*px + a0*py + g0
            float a0 = x2 - x1, b0 = y1 - y2, g0 = (y2 - y1) * x1 - (x2 - x1) * y1;
            float a1 = x0 - x2, b1 = y2 - y0, g1 = (y0 - y2) * x2 - (x0 - x2) * y2;
            float a2 = x1 - x0, b2 = y0 - y1, g2 = (y1 - y0) * x0 - (x1 - x0) * y0;
            g_cA[f] = make_float4(b0, a0, g0, b1);
            g_cB[f] = make_float4(a1, g1, b2, a2);
            g_cC[f] = make_float4(g2, s * z1 * z2, s * z0 * z2, s * z0 * z1);
            g_cZ[f] = s * z0 * z1 * z2;
        }
    }

    // ---- Phase B: bin all faces against this tile's padded bounds.
    int tx = tile & (TILES_X - 1);
    int ty = tile / TILES_X;
    float px_hi = 1.0f - 2.0f * ((float)(16 * tx) + 0.5f) / (float)WW + TPAD;
    float px_lo = 1.0f - 2.0f * ((float)(16 * tx + 15) + 0.5f) / (float)WW - TPAD;
    float py_hi = 1.0f - 2.0f * ((float)(16 * ty) + 0.5f) / (float)HH + TPAD;
    float py_lo = 1.0f - 2.0f * ((float)(16 * ty + 15) + 0.5f) / (float)HH - TPAD;

    const int FPW = FF / 8;                 // 125 faces per warp (ascending order)
    int base_f = warp * FPW;
    int cnt = 0;
#pragma unroll
    for (int r = 0; r < 4; ++r) {
        int fi = r * 32 + lane;
        int f  = base_f + fi;
        bool ov = false;
        if (fi < FPW) {
            int i0 = faces[f * 3 + 0];
            int i1 = faces[f * 3 + 1];
            int i2 = faces[f * 3 + 2];
            float x0 = verts[i0*3+0], y0 = verts[i0*3+1];
            float x1 = verts[i1*3+0], y1 = verts[i1*3+1];
            float x2 = verts[i2*3+0], y2 = verts[i2*3+1];
            float bxmin = fminf(x0, fminf(x1, x2));
            float bxmax = fmaxf(x0, fmaxf(x1, x2));
            float bymin = fminf(y0, fminf(y1, y2));
            float bymax = fmaxf(y0, fmaxf(y1, y2));
            ov = (bxmin <= px_hi) & (bxmax >= px_lo) &
                 (bymin <= py_hi) & (bymax >= py_lo);
            if (ov) {
                // Edge-normal SAT: reject if all 4 padded corners are strictly
                // outside any edge (s*w affine => max over rect at corners).
                float area = (x1 - x0) * (y2 - y0) - (y1 - y0) * (x2 - x0);
                float s = (area > EPSF) ? 1.0f :
                          (area < -EPSF ? -1.0f : CUDART_NAN_F);
                // NaN s: all comparisons false => face kept (harmless; fails inside)
#pragma unroll
                for (int e = 0; e < 3; ++e) {
                    float ax, ay, bx_, by_;
                    if (e == 0)      { ax = x1; ay = y1; bx_ = x2; by_ = y2; }
                    else if (e == 1) { ax = x2; ay = y2; bx_ = x0; by_ = y0; }
                    else             { ax = x0; ay = y0; bx_ = x1; by_ = y1; }
                    // w = (bx-ax)(py-ay) - (by-ay)(px-ax)
                    float aa = s * (bx_ - ax);     // coeff of py
                    float bb = s * (ay - by_);     // coeff of px
                    float gg = s * ((by_ - ay) * ax - (bx_ - ax) * ay);
                    float e00 = bb * px_lo + aa * py_lo + gg;
                    float e01 = bb * px_lo + aa * py_hi + gg;
                    float e10 = bb * px_hi + aa * py_lo + gg;
                    float e11 = bb * px_hi + aa * py_hi + gg;
                    float mx = fmaxf(fmaxf(e00, e01), fmaxf(e10, e11));
                    if (mx < ETHR) ov = false;
                }
            }
        }
        unsigned m = __ballot_sync(0xffffffffu, ov);
        if (lane == 0) s_mask[warp][r] = m;
        cnt += __popc(m);
    }
    if (lane == 0) s_wcnt[warp] = cnt;
    __syncthreads();
    if (tid == 0) {
        int acc = 0;
#pragma unroll
        for (int w = 0; w < 8; ++w) { s_woff[w] = acc; acc += s_wcnt[w]; }
        g_cnt[tile] = acc;
    }
    __syncthreads();
    {
        int off = s_woff[warp];
#pragma unroll
        for (int r = 0; r < 4; ++r) {
            unsigned m = s_mask[warp][r];
            if (m & (1u << lane))
                g_list[tile * FF + off + __popc(m & ((1u << lane) - 1u))]
                    = base_f + r * 32 + lane;
            off += __popc(m);
        }
    }
}

__device__ __forceinline__ float edge_d2(float ax, float ay, float bx, float by,
                                         float px, float py) {
    float ex = bx - ax, ey = by - ay;
    float l2 = fmaxf(ex * ex + ey * ey, EPSF);
    float t = ((px - ax) * ex + (py - ay) * ey) / l2;
    t = fminf(fmaxf(t, 0.0f), 1.0f);
    float dx = px - (ax + t * ex);
    float dy = py - (ay + t * ey);
    return dx * dx + dy * dy;
}

// Grid: 1024 blocks = 64 tiles x 16 rows. Block: 256 threads = 16 pixels x 16 chunks.
// smem staging capped at SCAP faces (~30.6KB). With regs<=42 ((256,6)) and 1024
// blocks, residency is ~6 blocks/SM -> ~75% occupancy AND the LDS broadcast path
// is kept (R11 showed removing smem costs 9us in L1 wavefronts; R12/13 showed
// 512 blocks is grid-limited to 3.5 blocks/SM).
__global__ __launch_bounds__(256, 6) void raster_kernel(
        const float* __restrict__ verts, const int* __restrict__ faces,
        float* __restrict__ out) {
    __shared__ float4 sA[SCAP];             //  8192 B
    __shared__ float4 sB[SCAP];             //  8192 B
    __shared__ float4 sC[SCAP];             //  8192 B
    __shared__ float  sZ[SCAP];             //  2048 B
    __shared__ int    s_idx[FF];            //  4000 B

    int tid  = threadIdx.x;
    int tile = blockIdx.x >> 4;
    int sb   = blockIdx.x & 15;
    int len  = g_cnt[tile];
    int lenc = min(len, SCAP);

    // Stage this tile's coefficient records (up to SCAP) + full index list.
    for (int i = tid; i < len; i += 256) {
        int f = g_list[tile * FF + i];
        s_idx[i] = f;
        if (i < SCAP) {
            sA[i] = g_cA[f];
            sB[i] = g_cB[f];
            sC[i] = g_cC[f];
            sZ[i] = g_cZ[f];
        }
    }
    __syncthreads();

    int p   = tid >> 4;         // pixel slot within block (0..15)
    int sub = tid & 15;         // face-chunk id (0..15)
    int tx  = tile & (TILES_X - 1);
    int ty  = tile / TILES_X;
    int x   = 16 * tx + p;
    int y   = 16 * ty + sb;     // sub-block owns one row of the tile
    int pix = y * WW + x;
    float px = 1.0f - 2.0f * ((float)x + 0.5f) / (float)WW;
    float py = 1.0f - 2.0f * ((float)y + 0.5f) / (float)HH;

    // Register-resident sorted top-8 (ascending z). Carries list POSITION.
    float zt[KK];
    int   it[KK];
#pragma unroll
    for (int k = 0; k < KK; k++) { zt[k] = BIGF; it[k] = -1; }

    // Main loop over smem-staged faces.
    for (int pos = sub; pos < lenc; pos += 16) {
        float4 a = sA[pos];
        float4 b = sB[pos];
        float4 c = sC[pos];
        float zzz = sZ[pos];

        float w0 = fmaf(a.x, px, fmaf(a.y, py, a.z));
        float w1 = fmaf(a.w, px, fmaf(b.x, py, b.y));
        float w2 = fmaf(b.z, px, fmaf(b.w, py, c.x));
        float m0 = w0 * c.y, m1 = w1 * c.z, m2 = w2 * c.w;

        if (fminf(m0, fminf(m1, m2)) >= 0.0f) {           // NaN (degenerate) fails
            float den = (m0 + m1) + m2;                   // > 0 when inside
            float num = zzz * ((w0 + w1) + w2);           // = m0*z0+m1*z1+m2*z2
            if (num < zt[KK - 1] * den) {                 // deferred division
                float zp = num / den;
                zt[KK - 1] = zp; it[KK - 1] = pos;
#pragma unroll
                for (int k = KK - 1; k > 0; --k) {
                    if (zt[k] < zt[k - 1]) {
                        float tz = zt[k]; zt[k] = zt[k - 1]; zt[k - 1] = tz;
                        int   ti = it[k]; it[k] = it[k - 1]; it[k - 1] = ti;
                    }
                }
            }
        }
    }
    // Rare tail: faces beyond the smem cap, read directly from global.
    for (int pos = ((lenc + 15 - sub) / 16) * 16 + sub; pos < len; pos += 16) {
        int f = s_idx[pos];
        float4 a = __ldg(g_cA + f);
        float4 b = __ldg(g_cB + f);
        float4 c = __ldg(g_cC + f);
        float zzz = __ldg(g_cZ + f);

        float w0 = fmaf(a.x, px, fmaf(a.y, py, a.z));
        float w1 = fmaf(a.w, px, fmaf(b.x, py, b.y));
        float w2 = fmaf(b.z, px, fmaf(b.w, py, c.x));
        float m0 = w0 * c.y, m1 = w1 * c.z, m2 = w2 * c.w;

        if (fminf(m0, fminf(m1, m2)) >= 0.0f) {
            float den = (m0 + m1) + m2;
            float num = zzz * ((w0 + w1) + w2);
            if (num < zt[KK - 1] * den) {
                float zp = num / den;
                zt[KK - 1] = zp; it[KK - 1] = pos;
#pragma unroll
                for (int k = KK - 1; k > 0; --k) {
                    if (zt[k] < zt[k - 1]) {
                        float tz = zt[k]; zt[k] = zt[k - 1]; zt[k - 1] = tz;
                        int   ti = it[k]; it[k] = it[k - 1]; it[k - 1] = ti;
                    }
                }
            }
        }
    }

    // Tree merge of the 16 sorted chunk-lists: rounds d=1,2,4,8. Active lanes
    // ((sub mod 2d)==0) insert their xor-partner's list; partners are inactive
    // for the whole round, so their zt/it stay original -> shuffle one value at
    // a time with NO buffer registers (keeps regs ~40, no spills).
    const unsigned FULLM = 0xffffffffu;
#pragma unroll
    for (int d = 1; d < 16; d <<= 1) {
        bool active = (sub & (2 * d - 1)) == 0;
#pragma unroll
        for (int k = 0; k < KK; k++) {
            float z = __shfl_xor_sync(FULLM, zt[k], d);
            int   i = __shfl_xor_sync(FULLM, it[k], d);
            if (active && z < zt[KK - 1]) {
                zt[KK - 1] = z; it[KK - 1] = i;
#pragma unroll
                for (int m = KK - 1; m > 0; --m) {
                    if (zt[m] < zt[m - 1]) {
                        float tz = zt[m]; zt[m] = zt[m - 1]; zt[m - 1] = tz;
                        int   ti = it[m]; it[m] = it[m - 1]; it[m - 1] = ti;
                    }
                }
            }
        }
    }

    // Redistribute: thread `sub` (sub<8) handles output slot k = sub.
    int lane = tid & 31;
    int base = lane & ~15;      // lane holding the merged list for this pixel
    float myz = BIGF; int mypos = -1;
#pragma unroll
    for (int k = 0; k < KK; k++) {
        float z = __shfl_sync(FULLM, zt[k], base);
        int   i = __shfl_sync(FULLM, it[k], base);
        if (sub == k) { myz = z; mypos = i; }
    }

    if (sub < KK) {
        int o = pix * KK + sub;
        float* o_p2f  = out;                // (H,W,K)
        float* o_zbuf = out + NSEC;         // (H,W,K)
        float* o_bary = out + 2 * NSEC;     // (H,W,K,3)
        float* o_dist = out + 5 * NSEC;     // (H,W,K)

        if (myz < 0.5f * BIGF) {
            int f = s_idx[mypos];
            float4 a, b, c;
            if (mypos < SCAP) { a = sA[mypos]; b = sB[mypos]; c = sC[mypos]; }
            else { a = __ldg(g_cA + f); b = __ldg(g_cB + f); c = __ldg(g_cC + f); }

            float w0 = fmaf(a.x, px, fmaf(a.y, py, a.z));
            float w1 = fmaf(a.w, px, fmaf(b.x, py, b.y));
            float w2 = fmaf(b.z, px, fmaf(b.w, py, c.x));
            float m0 = w0 * c.y, m1 = w1 * c.z, m2 = w2 * c.w;  // s cancels
            float inv = 1.0f / ((m0 + m1) + m2);
            float p0 = m0 * inv, p1 = m1 * inv, p2 = m2 * inv;

            // Vertex coords for edge distances: gather from L1-hot inputs.
            int i0 = faces[f * 3 + 0];
            int i1 = faces[f * 3 + 1];
            int i2 = faces[f * 3 + 2];
            float x0 = verts[i0*3+0], y0 = verts[i0*3+1];
            float x1 = verts[i1*3+0], y1 = verts[i1*3+1];
            float x2 = verts[i2*3+0], y2 = verts[i2*3+1];

            float d2 = fminf(edge_d2(x0, y0, x1, y1, px, py),
                       fminf(edge_d2(x1, y1, x2, y2, px, py),
                             edge_d2(x2, y2, x0, y0, px, py)));

            o_p2f[o]  = (float)f;
            o_zbuf[o] = myz;
            o_bary[o * 3 + 0] = p0;
            o_bary[o * 3 + 1] = p1;
            o_bary[o * 3 + 2] = p2;
            o_dist[o] = -d2;   // valid => inside => sd = -d2
        } else {
            o_p2f[o]  = -1.0f;
            o_zbuf[o] = -1.0f;
            o_bary[o * 3 + 0] = -1.0f;
            o_bary[o * 3 + 1] = -1.0f;
            o_bary[o * 3 + 2] = -1.0f;
            o_dist[o] = -1.0f;
        }
    }
}

extern "C" void kernel_launch(void* const* d_in, const int* in_sizes, int n_in,
                              void* d_out, int out_size) {
    // vertices: 1*600*3 = 1800 floats; faces: 1*1000*3 = 3000 ints.
    const float* verts;
    const int* faces;
    if (in_sizes[0] == 1800) {
        verts = (const float*)d_in[0];
        faces = (const int*)d_in[1];
    } else {
        verts = (const float*)d_in[1];
        faces = (const int*)d_in[0];
    }
    float* out = (float*)d_out;

    prep_bin<<<NTILES, 256>>>(verts, faces);
    raster_kernel<<<NTILES * 16, 256>>>(verts, faces, out);
}

// round 17
// speedup vs baseline: 1.1107x; 1.1107x over previous
#include <cuda_runtime.h>
#include <cuda_bf16.h>
#include <math_constants.h>

// Problem constants (fixed shapes for this problem instance)
#define HH   128
#define WW   128
#define FF   1000
#define KK   8
#define NPIX (HH * WW)            // 16384
#define NSEC (NPIX * KK)          // 131072 elements per (B,H,W,K) section
#define EPSF 1e-8f
#define BIGF 1e10f

#define TILES_X 8                 // 8x8 tiles of 16x16 pixels
#define NTILES  64
#define TPAD    1e-5f             // conservative tile-bound padding
#define ETHR   (-1e-5f)           // edge-corner reject threshold (covers fp error)
#define SCAP   512                // smem staging cap (post-SAT len ~200-300; tail path covers overflow)

// Per-face affine edge coefficients (w_i = b_i*px + a_i*py + g_i):
//  g_cA[f] = (b0, a0, g0, b1)
//  g_cB[f] = (a1, g1, b2, a2)
//  g_cC[f] = (g2, szz0, szz1, szz2)   szz_i = s*z_j*z_k, s=sign(area), NaN if degenerate
//  g_cZ[f] = s*z0*z1*z2
__device__ float4 g_cA[FF];
__device__ float4 g_cB[FF];
__device__ float4 g_cC[FF];
__device__ float  g_cZ[FF];
__device__ int    g_list[NTILES * FF];   // per-tile face lists (ascending)
__device__ int    g_cnt[NTILES];

// ONE prep kernel: 64 blocks (one per tile) x 256 threads.
// Phase A: block b computes coefficients for faces [b*16, b*16+16).
// Phase B: block b bins all faces against its tile: bbox SAT + edge-normal SAT
//          (exact conservative triangle-vs-rect overlap).
__global__ __launch_bounds__(256) void prep_bin(const float* __restrict__ verts,
                                                const int* __restrict__ faces) {
    __shared__ unsigned s_mask[8][4];
    __shared__ int s_wcnt[8];
    __shared__ int s_woff[8];

    int tile = blockIdx.x;
    int tid  = threadIdx.x;
    int warp = tid >> 5;
    int lane = tid & 31;

    // ---- Phase A: coefficients for this block's 16 faces.
    {
        int f = tile * 16 + tid;
        if (tid < 16 && f < FF) {
            int i0 = faces[f * 3 + 0];
            int i1 = faces[f * 3 + 1];
            int i2 = faces[f * 3 + 2];
            float x0 = verts[i0*3+0], y0 = verts[i0*3+1], z0 = verts[i0*3+2];
            float x1 = verts[i1*3+0], y1 = verts[i1*3+1], z1 = verts[i1*3+2];
            float x2 = verts[i2*3+0], y2 = verts[i2*3+1], z2 = verts[i2*3+2];
            float area = (x1 - x0) * (y2 - y0) - (y1 - y0) * (x2 - x0);
            float s;
            if (area > EPSF)       s = 1.0f;
            else if (area < -EPSF) s = -1.0f;
            else                   s = CUDART_NAN_F;  // NaN => inside-test fails
            // w0 = (x2-x1)(py-y1) - (y2-y1)(px-x1) = b0*px + a0*py + g0
            float a0 = x2 - x1, b0 = y1 - y2, g0 = (y2 - y1) * x1 - (x2 - x1) * y1;
            float a1 = x0 - x2, b1 = y2 - y0, g1 = (y0 - y2) * x2 - (x0 - x2) * y2;
            float a2 = x1 - x0, b2 = y0 - y1, g2 = (y1 - y0) * x0 - (x1 - x0) * y0;
            g_cA[f] = make_float4(b0, a0, g0, b1);
            g_cB[f] = make_float4(a1, g1, b2, a2);
            g_cC[f] = make_float4(g2, s * z1 * z2, s * z0 * z2, s * z0 * z1);
            g_cZ[f] = s * z0 * z1 * z2;
        }
    }

    // ---- Phase B: bin all faces against this tile's padded bounds.
    int tx = tile & (TILES_X - 1);
    int ty = tile / TILES_X;
    float px_hi = 1.0f - 2.0f * ((float)(16 * tx) + 0.5f) / (float)WW + TPAD;
    float px_lo = 1.0f - 2.0f * ((float)(16 * tx + 15) + 0.5f) / (float)WW - TPAD;
    float py_hi = 1.0f - 2.0f * ((float)(16 * ty) + 0.5f) / (float)HH + TPAD;
    float py_lo = 1.0f - 2.0f * ((float)(16 * ty + 15) + 0.5f) / (float)HH - TPAD;

    const int FPW = FF / 8;                 // 125 faces per warp (ascending order)
    int base_f = warp * FPW;
    int cnt = 0;
#pragma unroll
    for (int r = 0; r < 4; ++r) {
        int fi = r * 32 + lane;
        int f  = base_f + fi;
        bool ov = false;
        if (fi < FPW) {
            int i0 = faces[f * 3 + 0];
            int i1 = faces[f * 3 + 1];
            int i2 = faces[f * 3 + 2];
            float x0 = verts[i0*3+0], y0 = verts[i0*3+1];
            float x1 = verts[i1*3+0], y1 = verts[i1*3+1];
            float x2 = verts[i2*3+0], y2 = verts[i2*3+1];
            float bxmin = fminf(x0, fminf(x1, x2));
            float bxmax = fmaxf(x0, fmaxf(x1, x2));
            float bymin = fminf(y0, fminf(y1, y2));
            float bymax = fmaxf(y0, fmaxf(y1, y2));
            ov = (bxmin <= px_hi) & (bxmax >= px_lo) &
                 (bymin <= py_hi) & (bymax >= py_lo);
            if (ov) {
                // Edge-normal SAT: reject if all 4 padded corners are strictly
                // outside any edge (s*w affine => max over rect at corners).
                float area = (x1 - x0) * (y2 - y0) - (y1 - y0) * (x2 - x0);
                float s = (area > EPSF) ? 1.0f :
                          (area < -EPSF ? -1.0f : CUDART_NAN_F);
                // NaN s: all comparisons false => face kept (harmless; fails inside)
#pragma unroll
                for (int e = 0; e < 3; ++e) {
                    float ax, ay, bx_, by_;
                    if (e == 0)      { ax = x1; ay = y1; bx_ = x2; by_ = y2; }
                    else if (e == 1) { ax = x2; ay = y2; bx_ = x0; by_ = y0; }
                    else             { ax = x0; ay = y0; bx_ = x1; by_ = y1; }
                    // w = (bx-ax)(py-ay) - (by-ay)(px-ax)
                    float aa = s * (bx_ - ax);     // coeff of py
                    float bb = s * (ay - by_);     // coeff of px
                    float gg = s * ((by_ - ay) * ax - (bx_ - ax) * ay);
                    float e00 = bb * px_lo + aa * py_lo + gg;
                    float e01 = bb * px_lo + aa * py_hi + gg;
                    float e10 = bb * px_hi + aa * py_lo + gg;
                    float e11 = bb * px_hi + aa * py_hi + gg;
                    float mx = fmaxf(fmaxf(e00, e01), fmaxf(e10, e11));
                    if (mx < ETHR) ov = false;
                }
            }
        }
        unsigned m = __ballot_sync(0xffffffffu, ov);
        if (lane == 0) s_mask[warp][r] = m;
        cnt += __popc(m);
    }
    if (lane == 0) s_wcnt[warp] = cnt;
    __syncthreads();
    if (tid == 0) {
        int acc = 0;
#pragma unroll
        for (int w = 0; w < 8; ++w) { s_woff[w] = acc; acc += s_wcnt[w]; }
        g_cnt[tile] = acc;
    }
    __syncthreads();
    {
        int off = s_woff[warp];
#pragma unroll
        for (int r = 0; r < 4; ++r) {
            unsigned m = s_mask[warp][r];
            if (m & (1u << lane))
                g_list[tile * FF + off + __popc(m & ((1u << lane) - 1u))]
                    = base_f + r * 32 + lane;
            off += __popc(m);
        }
    }
}

__device__ __forceinline__ float edge_d2(float ax, float ay, float bx, float by,
                                         float px, float py) {
    float ex = bx - ax, ey = by - ay;
    float l2 = fmaxf(ex * ex + ey * ey, EPSF);
    float t = ((px - ax) * ex + (py - ay) * ey) / l2;
    t = fminf(fmaxf(t, 0.0f), 1.0f);
    float dx = px - (ax + t * ex);
    float dy = py - (ay + t * ey);
    return dx * dx + dy * dy;
}

// Grid: 1024 blocks = 64 tiles x 16 rows. Block: 128 threads = 16 pixels x 8 chunks.
// Same per-thread work shape as the best kernel (8 subs, 3 merge rounds, smem
// broadcast), but 128-thread blocks let ~7 blocks co-reside per SM (31KB smem,
// 40 regs) -> ~85% theoretical occupancy vs 30% when grid-limited at 512x256.
__global__ __launch_bounds__(128, 7) void raster_kernel(
        const float* __restrict__ verts, const int* __restrict__ faces,
        float* __restrict__ out) {
    __shared__ float4 sA[SCAP];             //  8192 B
    __shared__ float4 sB[SCAP];             //  8192 B
    __shared__ float4 sC[SCAP];             //  8192 B
    __shared__ float  sZ[SCAP];             //  2048 B
    __shared__ int    s_idx[FF];            //  4000 B

    int tid  = threadIdx.x;
    int tile = blockIdx.x >> 4;
    int sb   = blockIdx.x & 15;
    int len  = g_cnt[tile];
    int lenc = min(len, SCAP);

    // Stage this tile's coefficient records (up to SCAP) + full index list.
    for (int i = tid; i < len; i += 128) {
        int f = g_list[tile * FF + i];
        s_idx[i] = f;
        if (i < SCAP) {
            sA[i] = g_cA[f];
            sB[i] = g_cB[f];
            sC[i] = g_cC[f];
            sZ[i] = g_cZ[f];
        }
    }
    __syncthreads();

    int p   = tid >> 3;         // pixel slot within block (0..15)
    int sub = tid & 7;          // face-chunk id (0..7)
    int tx  = tile & (TILES_X - 1);
    int ty  = tile / TILES_X;
    int x   = 16 * tx + p;
    int y   = 16 * ty + sb;     // sub-block owns one row of the tile
    int pix = y * WW + x;
    float px = 1.0f - 2.0f * ((float)x + 0.5f) / (float)WW;
    float py = 1.0f - 2.0f * ((float)y + 0.5f) / (float)HH;

    // Register-resident sorted top-8 (ascending z). Carries list POSITION.
    float zt[KK];
    int   it[KK];
#pragma unroll
    for (int k = 0; k < KK; k++) { zt[k] = BIGF; it[k] = -1; }

    // Main loop over smem-staged faces.
    for (int pos = sub; pos < lenc; pos += 8) {
        float4 a = sA[pos];
        float4 b = sB[pos];
        float4 c = sC[pos];
        float zzz = sZ[pos];

        float w0 = fmaf(a.x, px, fmaf(a.y, py, a.z));
        float w1 = fmaf(a.w, px, fmaf(b.x, py, b.y));
        float w2 = fmaf(b.z, px, fmaf(b.w, py, c.x));
        float m0 = w0 * c.y, m1 = w1 * c.z, m2 = w2 * c.w;

        if (fminf(m0, fminf(m1, m2)) >= 0.0f) {           // NaN (degenerate) fails
            float den = (m0 + m1) + m2;                   // > 0 when inside
            float num = zzz * ((w0 + w1) + w2);           // = m0*z0+m1*z1+m2*z2
            if (num < zt[KK - 1] * den) {                 // deferred division
                float zp = num / den;
                zt[KK - 1] = zp; it[KK - 1] = pos;
#pragma unroll
                for (int k = KK - 1; k > 0; --k) {
                    if (zt[k] < zt[k - 1]) {
                        float tz = zt[k]; zt[k] = zt[k - 1]; zt[k - 1] = tz;
                        int   ti = it[k]; it[k] = it[k - 1]; it[k - 1] = ti;
                    }
                }
            }
        }
    }
    // Rare tail: faces beyond the smem cap, read directly from global.
    for (int pos = ((lenc + 7 - sub) / 8) * 8 + sub; pos < len; pos += 8) {
        int f = s_idx[pos];
        float4 a = __ldg(g_cA + f);
        float4 b = __ldg(g_cB + f);
        float4 c = __ldg(g_cC + f);
        float zzz = __ldg(g_cZ + f);

        float w0 = fmaf(a.x, px, fmaf(a.y, py, a.z));
        float w1 = fmaf(a.w, px, fmaf(b.x, py, b.y));
        float w2 = fmaf(b.z, px, fmaf(b.w, py, c.x));
        float m0 = w0 * c.y, m1 = w1 * c.z, m2 = w2 * c.w;

        if (fminf(m0, fminf(m1, m2)) >= 0.0f) {
            float den = (m0 + m1) + m2;
            float num = zzz * ((w0 + w1) + w2);
            if (num < zt[KK - 1] * den) {
                float zp = num / den;
                zt[KK - 1] = zp; it[KK - 1] = pos;
#pragma unroll
                for (int k = KK - 1; k > 0; --k) {
                    if (zt[k] < zt[k - 1]) {
                        float tz = zt[k]; zt[k] = zt[k - 1]; zt[k - 1] = tz;
                        int   ti = it[k]; it[k] = it[k - 1]; it[k - 1] = ti;
                    }
                }
            }
        }
    }

    // Tree merge of the 8 sorted chunk-lists: rounds d=1,2,4. Active lanes
    // ((sub mod 2d)==0) insert their xor-partner's list; partners are inactive
    // for the whole round, so their zt/it stay original -> shuffle one value at
    // a time with NO buffer registers (keeps regs ~40, no spills).
    const unsigned FULLM = 0xffffffffu;
#pragma unroll
    for (int d = 1; d < 8; d <<= 1) {
        bool active = (sub & (2 * d - 1)) == 0;
#pragma unroll
        for (int k = 0; k < KK; k++) {
            float z = __shfl_xor_sync(FULLM, zt[k], d);
            int   i = __shfl_xor_sync(FULLM, it[k], d);
            if (active && z < zt[KK - 1]) {
                zt[KK - 1] = z; it[KK - 1] = i;
#pragma unroll
                for (int m = KK - 1; m > 0; --m) {
                    if (zt[m] < zt[m - 1]) {
                        float tz = zt[m]; zt[m] = zt[m - 1]; zt[m - 1] = tz;
                        int   ti = it[m]; it[m] = it[m - 1]; it[m - 1] = ti;
                    }
                }
            }
        }
    }

    // Redistribute: thread `sub` handles output slot k = sub of its pixel.
    int lane = tid & 31;
    int base = lane & ~7;       // lane holding the merged list for this pixel
    float myz = BIGF; int mypos = -1;
#pragma unroll
    for (int k = 0; k < KK; k++) {
        float z = __shfl_sync(FULLM, zt[k], base);
        int   i = __shfl_sync(FULLM, it[k], base);
        if (sub == k) { myz = z; mypos = i; }
    }

    int o = pix * KK + sub;
    float* o_p2f  = out;                // (H,W,K)
    float* o_zbuf = out + NSEC;         // (H,W,K)
    float* o_bary = out + 2 * NSEC;     // (H,W,K,3)
    float* o_dist = out + 5 * NSEC;     // (H,W,K)

    if (myz < 0.5f * BIGF) {
        int f = s_idx[mypos];
        float4 a, b, c;
        if (mypos < SCAP) { a = sA[mypos]; b = sB[mypos]; c = sC[mypos]; }
        else { a = __ldg(g_cA + f); b = __ldg(g_cB + f); c = __ldg(g_cC + f); }

        float w0 = fmaf(a.x, px, fmaf(a.y, py, a.z));
        float w1 = fmaf(a.w, px, fmaf(b.x, py, b.y));
        float w2 = fmaf(b.z, px, fmaf(b.w, py, c.x));
        float m0 = w0 * c.y, m1 = w1 * c.z, m2 = w2 * c.w;   // s cancels in ratios
        float inv = 1.0f / ((m0 + m1) + m2);
        float p0 = m0 * inv, p1 = m1 * inv, p2 = m2 * inv;

        // Vertex coords for edge distances: gather from L1-hot inputs.
        int i0 = faces[f * 3 + 0];
        int i1 = faces[f * 3 + 1];
        int i2 = faces[f * 3 + 2];
        float x0 = verts[i0*3+0], y0 = verts[i0*3+1];
        float x1 = verts[i1*3+0], y1 = verts[i1*3+1];
        float x2 = verts[i2*3+0], y2 = verts[i2*3+1];

        float d2 = fminf(edge_d2(x0, y0, x1, y1, px, py),
                   fminf(edge_d2(x1, y1, x2, y2, px, py),
                         edge_d2(x2, y2, x0, y0, px, py)));

        o_p2f[o]  = (float)f;
        o_zbuf[o] = myz;
        o_bary[o * 3 + 0] = p0;
        o_bary[o * 3 + 1] = p1;
        o_bary[o * 3 + 2] = p2;
        o_dist[o] = -d2;   // valid => inside => sd = -d2
    } else {
        o_p2f[o]  = -1.0f;
        o_zbuf[o] = -1.0f;
        o_bary[o * 3 + 0] = -1.0f;
        o_bary[o * 3 + 1] = -1.0f;
        o_bary[o * 3 + 2] = -1.0f;
        o_dist[o] = -1.0f;
    }
}

extern "C" void kernel_launch(void* const* d_in, const int* in_sizes, int n_in,
                              void* d_out, int out_size) {
    // vertices: 1*600*3 = 1800 floats; faces: 1*1000*3 = 3000 ints.
    const float* verts;
    const int* faces;
    if (in_sizes[0] == 1800) {
        verts = (const float*)d_in[0];
        faces = (const int*)d_in[1];
    } else {
        verts = (const float*)d_in[1];
        faces = (const int*)d_in[0];
    }
    float* out = (float*)d_out;

    prep_bin<<<NTILES, 256>>>(verts, faces);
    raster_kernel<<<NTILES * 16, 128>>>(verts, faces, out);
}